// round 1
// baseline (speedup 1.0000x reference)
#include <cuda_runtime.h>
#include <cstdint>

#define MAXB 64
#define MAXP 8800
#define MAXN 64

// ---------------- scratch (device globals; no allocation) ----------------
__device__ int                g_bti[MAXB * MAXP];     // best_truth_idx
__device__ float              g_bto[MAXB * MAXP];     // best_truth_ovl
__device__ float              g_lossc[MAXB * MAXP];   // loss_c (0 for pos)
__device__ unsigned long long g_key[MAXB * MAXN];     // per-GT best prior key
__device__ int                g_numpos[MAXB];
__device__ double             g_acc[3];               // loc, ce_pos, ce_neg

// ---------------- reductions ----------------
__device__ __forceinline__ double warpSumD(double v) {
#pragma unroll
    for (int o = 16; o; o >>= 1) v += __shfl_down_sync(0xFFFFFFFFu, v, o);
    return v;
}
__device__ __forceinline__ int warpSumI(int v) {
#pragma unroll
    for (int o = 16; o; o >>= 1) v += __shfl_down_sync(0xFFFFFFFFu, v, o);
    return v;
}

__device__ int blockSumI(int v, int* sh) {
    __syncthreads();
    int lane = threadIdx.x & 31, wid = threadIdx.x >> 5;
    v = warpSumI(v);
    if (lane == 0) sh[wid] = v;
    __syncthreads();
    if (wid == 0) {
        int nw = (blockDim.x + 31) >> 5;
        int x = (lane < nw) ? sh[lane] : 0;
        x = warpSumI(x);
        if (lane == 0) sh[0] = x;
    }
    __syncthreads();
    return sh[0];
}

__device__ double blockSumD(double v, double* sh) {
    __syncthreads();
    int lane = threadIdx.x & 31, wid = threadIdx.x >> 5;
    v = warpSumD(v);
    if (lane == 0) sh[wid] = v;
    __syncthreads();
    if (wid == 0) {
        int nw = (blockDim.x + 31) >> 5;
        double x = (lane < nw) ? sh[lane] : 0.0;
        x = warpSumD(x);
        if (lane == 0) sh[0] = x;
    }
    __syncthreads();
    return sh[0];
}

// ---------------- kernel 0: init ----------------
__global__ void k_init(int B, int NMAX) {
    int i = blockIdx.x * blockDim.x + threadIdx.x;
    if (i < B * NMAX) g_key[i] = 0xFFFFFFFFull;  // iou=0, p=0 baseline
    if (i < B) g_numpos[i] = 0;
    if (i < 3) g_acc[i] = 0.0;
}

// ---------------- kernel 1: matching ----------------
// grid: (ceil(P/256), B) x 256
__global__ void k_match(const float* __restrict__ priors,
                        const float* __restrict__ labels,
                        const int* __restrict__ obj_count,
                        int P, int NMAX) {
    int b = blockIdx.y;
    int p = blockIdx.x * blockDim.x + threadIdx.x;

    __shared__ float4 sh_box[MAXN];
    __shared__ float  sh_area[MAXN];
    __shared__ unsigned long long sh_key[MAXN];
    __shared__ unsigned int sh_best[MAXN];

    int nv = obj_count[b];
    if (nv > NMAX) nv = NMAX;

    for (int n = threadIdx.x; n < NMAX; n += blockDim.x) {
        const float* g = labels + ((size_t)b * NMAX + n) * 5;
        float x0 = g[0], y0 = g[1], x1 = g[2], y1 = g[3];
        sh_box[n] = make_float4(x0, y0, x1, y1);
        sh_area[n] = (x1 - x0) * (y1 - y0);
        sh_key[n] = 0ull;
        sh_best[n] = 0u;
    }
    __syncthreads();

    if (p < P) {
        float cx = priors[p * 4 + 0], cy = priors[p * 4 + 1];
        float w = priors[p * 4 + 2], h = priors[p * 4 + 3];
        float px0 = cx - 0.5f * w, py0 = cy - 0.5f * h;
        float px1 = cx + 0.5f * w, py1 = cy + 0.5f * h;
        float ab = (px1 - px0) * (py1 - py0);

        float bestI = -1.0f, bestU = 1.0f;
        int bestN = 0;

        for (int n = 0; n < nv; n++) {
            float4 g = sh_box[n];
            float iw = fminf(px1, g.z) - fmaxf(px0, g.x);
            float ih = fminf(py1, g.w) - fmaxf(py0, g.y);
            if (fminf(iw, ih) > 0.0f) {
                float inter = iw * ih;
                float uni = sh_area[n] + ab - inter;
                // per-prior argmax over n (cross-multiplied compare, ties keep first)
                if (inter * bestU > bestI * uni) { bestI = inter; bestU = uni; bestN = n; }
                // per-GT argmax over p (division only when strictly improving)
                float cur = __uint_as_float(sh_best[n]);
                if (inter > cur * uni) {
                    float iou = inter / uni;
                    unsigned int ib = __float_as_uint(iou);
                    atomicMax(&sh_best[n], ib);
                    unsigned long long key =
                        ((unsigned long long)ib << 32) |
                        (unsigned long long)(0xFFFFFFFFu - (unsigned)p);
                    atomicMax(&sh_key[n], key);
                }
            }
        }
        size_t bp = (size_t)b * P + p;
        g_bti[bp] = bestN;
        g_bto[bp] = (bestI > 0.0f) ? (bestI / bestU) : 0.0f;
    }
    __syncthreads();
    for (int n = threadIdx.x; n < nv; n += blockDim.x)
        if (sh_key[n]) atomicMax(&g_key[(size_t)b * NMAX + n], sh_key[n]);
}

// ---------------- kernel 2: override (sequential per batch, last-n wins) ----------------
__global__ void k_override(const int* __restrict__ obj_count, int B, int P, int NMAX) {
    int b = blockIdx.x * blockDim.x + threadIdx.x;
    if (b >= B) return;
    int nv = obj_count[b];
    if (nv > NMAX) nv = NMAX;
    for (int n = 0; n < nv; n++) {
        unsigned long long key = g_key[(size_t)b * NMAX + n];
        unsigned int p = 0xFFFFFFFFu - (unsigned int)(key & 0xFFFFFFFFull);
        size_t bp = (size_t)b * P + p;
        g_bto[bp] = 2.0f;
        g_bti[bp] = n;
    }
}

// ---------------- kernel 3: per-anchor losses ----------------
// grid: (ceil(P/128), B) x 128
template <int C>
__global__ void k_loss(const float* __restrict__ conf,
                       const float* __restrict__ loc,
                       const float* __restrict__ priors,
                       const float* __restrict__ labels,
                       int P, int NMAX) {
    int b = blockIdx.y;
    int p = blockIdx.x * blockDim.x + threadIdx.x;
    double myloc = 0.0, myce = 0.0;
    int mypos = 0;

    if (p < P) {
        size_t bp = (size_t)b * P + p;
        int n = g_bti[bp];
        float ovl = g_bto[bp];
        const float* gt = labels + ((size_t)b * NMAX + n) * 5;
        int ct = (ovl < 0.5f) ? 0 : ((int)gt[4] + 1);

        const float* cr = conf + bp * C;
        float vv[C];
        float m = -1e30f;
#pragma unroll
        for (int c = 0; c < C; c++) { float x = cr[c]; vv[c] = x; m = fmaxf(m, x); }
        float s = 0.0f, tgt = 0.0f;
#pragma unroll
        for (int c = 0; c < C; c++) {
            s += __expf(vv[c] - m);
            if (c == ct) tgt = vv[c];
        }
        float ce = __logf(s) + m - tgt;
        bool pos = (ct > 0);
        g_lossc[bp] = pos ? 0.0f : ce;

        if (pos) {
            mypos = 1;
            myce = (double)ce;
            float cx = priors[p * 4 + 0], cy = priors[p * 4 + 1];
            float w = priors[p * 4 + 2], h = priors[p * 4 + 3];
            float t0 = ((gt[0] + gt[2]) * 0.5f - cx) / (0.1f * w);
            float t1 = ((gt[1] + gt[3]) * 0.5f - cy) / (0.1f * h);
            float t2 = __logf((gt[2] - gt[0]) / w) / 0.2f;
            float t3 = __logf((gt[3] - gt[1]) / h) / 0.2f;
            float t[4] = {t0, t1, t2, t3};
            const float* lr = loc + bp * 4;
            float acc = 0.0f;
#pragma unroll
            for (int i = 0; i < 4; i++) {
                float d = fabsf(lr[i] - t[i]);
                acc += (d < 1.0f) ? 0.5f * d * d : d - 0.5f;
            }
            myloc = (double)acc;
        }
    }

    __shared__ double shd0[4], shd1[4];
    __shared__ int shi[4];
    int lane = threadIdx.x & 31, wid = threadIdx.x >> 5;
    myloc = warpSumD(myloc);
    myce = warpSumD(myce);
    mypos = warpSumI(mypos);
    if (lane == 0) { shd0[wid] = myloc; shd1[wid] = myce; shi[wid] = mypos; }
    __syncthreads();
    if (threadIdx.x == 0) {
        double a = 0.0, c2 = 0.0; int cp = 0;
        for (int w = 0; w < 4; w++) { a += shd0[w]; c2 += shd1[w]; cp += shi[w]; }
        if (a != 0.0) atomicAdd(&g_acc[0], a);
        if (c2 != 0.0) atomicAdd(&g_acc[1], c2);
        if (cp) atomicAdd(&g_numpos[blockIdx.y], cp);
    }
}

// ---------------- kernel 4: top-k negative selection (value-sum, tie-exact) ----------------
// grid: B blocks x 1024
__global__ void k_select(int P) {
    int b = blockIdx.x;
    __shared__ unsigned int sv[MAXP];
    __shared__ int s_ri[32];
    __shared__ double s_rd[32];
    int tid = threadIdx.x, nt = blockDim.x;

    for (int i = tid; i < P; i += nt)
        sv[i] = __float_as_uint(g_lossc[(size_t)b * P + i]);
    __syncthreads();

    int npos = g_numpos[b];
    int k = 3 * npos;
    if (k > P - 1) k = P - 1;

    // max x with count(v >= x) >= k   (v >= 0 -> uint-ordered)
    unsigned int lo = 0, hi = 0x7F800000u;
    while (lo < hi) {
        unsigned int mid = lo + ((hi - lo + 1u) >> 1);
        int c = 0;
        for (int i = tid; i < P; i += nt) c += (sv[i] >= mid);
        c = blockSumI(c, s_ri);
        if (c >= k) lo = mid; else hi = mid - 1u;
    }
    unsigned int T = lo;

    int c1 = 0; double s1 = 0.0;
    for (int i = tid; i < P; i += nt) {
        unsigned int v = sv[i];
        if (v > T) { c1++; s1 += (double)__uint_as_float(v); }
    }
    c1 = blockSumI(c1, s_ri);
    s1 = blockSumD(s1, s_rd);
    if (tid == 0)
        atomicAdd(&g_acc[2], s1 + (double)(k - c1) * (double)__uint_as_float(T));
}

// ---------------- kernel 5: finalize ----------------
__global__ void k_final(float* out, int B) {
    if (threadIdx.x == 0) {
        long long N = 0;
        for (int b = 0; b < B; b++) N += g_numpos[b];
        double Nd = (double)N;
        out[0] = (float)(g_acc[0] / Nd);
        out[1] = (float)((g_acc[1] + g_acc[2]) / Nd);
    }
}

// ---------------- launch ----------------
extern "C" void kernel_launch(void* const* d_in, const int* in_sizes, int n_in,
                              void* d_out, int out_size) {
    const float* conf   = (const float*)d_in[0];
    const float* loc    = (const float*)d_in[1];
    const float* priors = (const float*)d_in[2];
    const float* labels = (const float*)d_in[3];
    const int*   obj    = (const int*)d_in[4];

    int P = in_sizes[2] / 4;
    int B = in_sizes[4];
    int C = (int)((long long)in_sizes[0] / ((long long)B * P));
    int NMAX = in_sizes[3] / (B * 5);

    k_init<<<(B * NMAX + 255) / 256, 256>>>(B, NMAX);

    dim3 gm((P + 255) / 256, B);
    k_match<<<gm, 256>>>(priors, labels, obj, P, NMAX);

    k_override<<<1, 128>>>(obj, B, P, NMAX);

    dim3 gl((P + 127) / 128, B);
    if (C == 21) {
        k_loss<21><<<gl, 128>>>(conf, loc, priors, labels, P, NMAX);
    } else if (C == 81) {
        k_loss<81><<<gl, 128>>>(conf, loc, priors, labels, P, NMAX);
    }

    k_select<<<B, 1024>>>(P);
    k_final<<<1, 32>>>((float*)d_out, B);
}

// round 2
// speedup vs baseline: 1.3242x; 1.3242x over previous
#include <cuda_runtime.h>
#include <cstdint>

#define MAXB 64
#define MAXP 8800
#define MAXN 64

// ---------------- scratch (device globals; no allocation) ----------------
__device__ int                g_bti[MAXB * MAXP];     // best_truth_idx
__device__ int                g_pos0[MAXB * MAXP];    // iou >= 0.5 flag (pre-override)
__device__ int                g_ovr[MAXB * MAXP];     // override: n+1 of forced GT, 0 = none
__device__ float              g_lossc[MAXB * MAXP];   // loss_c (0 for pos)
__device__ unsigned long long g_key[MAXB * MAXN];     // per-GT best prior key
__device__ int                g_numpos[MAXB];
__device__ double             g_acc[3];               // loc, ce_pos, ce_neg

// ---------------- reductions ----------------
__device__ __forceinline__ double warpSumD(double v) {
#pragma unroll
    for (int o = 16; o; o >>= 1) v += __shfl_down_sync(0xFFFFFFFFu, v, o);
    return v;
}
__device__ __forceinline__ int warpSumI(int v) {
#pragma unroll
    for (int o = 16; o; o >>= 1) v += __shfl_down_sync(0xFFFFFFFFu, v, o);
    return v;
}

__device__ int blockSumI(int v, int* sh) {
    __syncthreads();
    int lane = threadIdx.x & 31, wid = threadIdx.x >> 5;
    v = warpSumI(v);
    if (lane == 0) sh[wid] = v;
    __syncthreads();
    if (wid == 0) {
        int nw = (blockDim.x + 31) >> 5;
        int x = (lane < nw) ? sh[lane] : 0;
        x = warpSumI(x);
        if (lane == 0) sh[0] = x;
    }
    __syncthreads();
    return sh[0];
}

__device__ double blockSumD(double v, double* sh) {
    __syncthreads();
    int lane = threadIdx.x & 31, wid = threadIdx.x >> 5;
    v = warpSumD(v);
    if (lane == 0) sh[wid] = v;
    __syncthreads();
    if (wid == 0) {
        int nw = (blockDim.x + 31) >> 5;
        double x = (lane < nw) ? sh[lane] : 0.0;
        x = warpSumD(x);
        if (lane == 0) sh[0] = x;
    }
    __syncthreads();
    return sh[0];
}

// ---------------- kernel 0: init ----------------
__global__ void k_init(int B, int NMAX) {
    int i = blockIdx.x * blockDim.x + threadIdx.x;
    if (i < B * NMAX) g_key[i] = 0xFFFFFFFFull;
    if (i < B) g_numpos[i] = 0;
    if (i < 3) g_acc[i] = 0.0;
}

// ---------------- kernel 1: matching ----------------
// grid: (ceil(P/256), B) x 256
__global__ void k_match(const float* __restrict__ priors,
                        const float* __restrict__ labels,
                        const int* __restrict__ obj_count,
                        int P, int NMAX) {
    int b = blockIdx.y;
    int p = blockIdx.x * blockDim.x + threadIdx.x;

    __shared__ float4 sh_box[MAXN];
    __shared__ float  sh_area[MAXN];
    __shared__ unsigned long long sh_key[MAXN];
    __shared__ unsigned int sh_best[MAXN];

    int nv = obj_count[b];
    if (nv > NMAX) nv = NMAX;

    for (int n = threadIdx.x; n < NMAX; n += blockDim.x) {
        const float* g = labels + ((size_t)b * NMAX + n) * 5;
        float x0 = g[0], y0 = g[1], x1 = g[2], y1 = g[3];
        sh_box[n] = make_float4(x0, y0, x1, y1);
        sh_area[n] = (x1 - x0) * (y1 - y0);
        sh_key[n] = 0ull;
        sh_best[n] = 0u;
    }
    __syncthreads();

    if (p < P) {
        float4 pr = reinterpret_cast<const float4*>(priors)[p];
        float px0 = pr.x - 0.5f * pr.z, py0 = pr.y - 0.5f * pr.w;
        float px1 = pr.x + 0.5f * pr.z, py1 = pr.y + 0.5f * pr.w;
        float ab = pr.z * pr.w;

        float bestI = -1.0f, bestU = 1.0f;
        int bestN = 0;

        for (int n = 0; n < nv; n++) {
            float4 g = sh_box[n];
            float iw = fminf(px1, g.z) - fmaxf(px0, g.x);
            float ih = fminf(py1, g.w) - fmaxf(py0, g.y);
            if (fminf(iw, ih) > 0.0f) {
                float inter = iw * ih;
                float uni = sh_area[n] + ab - inter;
                // per-prior argmax over n (cross-multiplied; ties keep first)
                if (inter * bestU > bestI * uni) { bestI = inter; bestU = uni; bestN = n; }
                // per-GT argmax over p (division only on strict improvement)
                float cur = __uint_as_float(sh_best[n]);
                if (inter > cur * uni) {
                    float iou = inter / uni;
                    unsigned int ib = __float_as_uint(iou);
                    atomicMax(&sh_best[n], ib);
                    unsigned long long key =
                        ((unsigned long long)ib << 32) |
                        (unsigned long long)(0xFFFFFFFFu - (unsigned)p);
                    atomicMax(&sh_key[n], key);
                }
            }
        }
        size_t bp = (size_t)b * P + p;
        g_bti[bp] = bestN;
        g_pos0[bp] = (bestI > 0.0f && bestI >= 0.5f * bestU) ? 1 : 0;
        g_ovr[bp] = 0;
    }
    __syncthreads();
    for (int n = threadIdx.x; n < nv; n += blockDim.x)
        if (sh_key[n]) atomicMax(&g_key[(size_t)b * NMAX + n], sh_key[n]);
}

// ---------------- kernel 2: override (parallel; highest n wins == last-wins) ----------------
__global__ void k_override(const int* __restrict__ obj_count, int P, int NMAX) {
    int b = blockIdx.x;
    int n = threadIdx.x;
    int nv = obj_count[b];
    if (nv > NMAX) nv = NMAX;
    if (n < nv) {
        unsigned long long key = g_key[(size_t)b * NMAX + n];
        unsigned int p = 0xFFFFFFFFu - (unsigned int)(key & 0xFFFFFFFFull);
        atomicMax(&g_ovr[(size_t)b * P + p], n + 1);
    }
}

// ---------------- kernel 3: per-anchor losses (smem-staged conf) ----------------
// grid: (ceil(P/128), B) x 128
template <int C>
__global__ void k_loss(const float* __restrict__ conf,
                       const float* __restrict__ loc,
                       const float* __restrict__ priors,
                       const float* __restrict__ labels,
                       int P, int NMAX) {
    __shared__ float shc[128 * C];
    int tid = threadIdx.x;
    int b = blockIdx.y;
    int p0 = blockIdx.x * 128;
    int cnt = min(128, P - p0);
    size_t base = ((size_t)b * P + p0) * C;
    int tot = cnt * C;

    // coalesced staging; float4 fast path when aligned & divisible
    if (((base & 3) == 0) && ((tot & 3) == 0)) {
        const float4* s4 = reinterpret_cast<const float4*>(conf + base);
        float4* d4 = reinterpret_cast<float4*>(shc);
        int t4 = tot >> 2;
        for (int i = tid; i < t4; i += blockDim.x) d4[i] = s4[i];
    } else {
        for (int i = tid; i < tot; i += blockDim.x) shc[i] = conf[base + i];
    }
    __syncthreads();

    double myloc = 0.0, myce = 0.0;
    int mypos = 0;
    int p = p0 + tid;

    if (p < P) {
        size_t bp = (size_t)b * P + p;
        int ovr = g_ovr[bp];
        int n;  bool posmatch;
        if (ovr > 0) { n = ovr - 1; posmatch = true; }
        else         { n = g_bti[bp]; posmatch = (g_pos0[bp] != 0); }

        const float* gt = labels + ((size_t)b * NMAX + n) * 5;
        int ct = posmatch ? ((int)gt[4] + 1) : 0;

        const float* vv = shc + tid * C;
        float m = vv[0];
#pragma unroll
        for (int c = 1; c < C; c++) m = fmaxf(m, vv[c]);
        float s = 0.0f, tgt = 0.0f;
#pragma unroll
        for (int c = 0; c < C; c++) {
            s += __expf(vv[c] - m);
            if (c == ct) tgt = vv[c];
        }
        float ce = __logf(s) + m - tgt;
        bool pos = (ct > 0);
        g_lossc[bp] = pos ? 0.0f : ce;

        if (pos) {
            mypos = 1;
            myce = (double)ce;
            float4 pr = reinterpret_cast<const float4*>(priors)[p];
            float t0 = ((gt[0] + gt[2]) * 0.5f - pr.x) / (0.1f * pr.z);
            float t1 = ((gt[1] + gt[3]) * 0.5f - pr.y) / (0.1f * pr.w);
            float t2 = __logf((gt[2] - gt[0]) / pr.z) / 0.2f;
            float t3 = __logf((gt[3] - gt[1]) / pr.w) / 0.2f;
            float4 lr = reinterpret_cast<const float4*>(loc)[bp];
            float t[4] = {t0, t1, t2, t3};
            float l[4] = {lr.x, lr.y, lr.z, lr.w};
            float acc = 0.0f;
#pragma unroll
            for (int i = 0; i < 4; i++) {
                float d = fabsf(l[i] - t[i]);
                acc += (d < 1.0f) ? 0.5f * d * d : d - 0.5f;
            }
            myloc = (double)acc;
        }
    }

    __shared__ double shd0[4], shd1[4];
    __shared__ int shi[4];
    int lane = threadIdx.x & 31, wid = threadIdx.x >> 5;
    myloc = warpSumD(myloc);
    myce = warpSumD(myce);
    mypos = warpSumI(mypos);
    if (lane == 0) { shd0[wid] = myloc; shd1[wid] = myce; shi[wid] = mypos; }
    __syncthreads();
    if (threadIdx.x == 0) {
        double a = 0.0, c2 = 0.0; int cp = 0;
        for (int w = 0; w < 4; w++) { a += shd0[w]; c2 += shd1[w]; cp += shi[w]; }
        if (a != 0.0) atomicAdd(&g_acc[0], a);
        if (c2 != 0.0) atomicAdd(&g_acc[1], c2);
        if (cp) atomicAdd(&g_numpos[blockIdx.y], cp);
    }
}

// ---------------- kernel 4: radix top-k negative selection (tie-exact) ----------------
// grid: B blocks x 1024
__global__ void k_select(int P) {
    int b = blockIdx.x;
    __shared__ unsigned int sv[MAXP];
    __shared__ int hist[2048];
    __shared__ int s_ri[32];
    __shared__ double s_rd[32];
    __shared__ int s_sel;
    int tid = threadIdx.x, nt = blockDim.x;

    for (int i = tid; i < P; i += nt)
        sv[i] = __float_as_uint(g_lossc[(size_t)b * P + i]);

    int npos = g_numpos[b];
    int k = 3 * npos;
    if (k > P - 1) k = P - 1;
    __syncthreads();
    if (k <= 0) return;

    // radix select: find T = k-th largest uint (loss_c >= 0 -> uint-ordered)
    unsigned int prefix = 0;
    int kk = k;
    const int bitsArr[3] = {11, 11, 10};
    const int shiftArr[3] = {21, 10, 0};

    for (int r = 0; r < 3; r++) {
        int bits = bitsArr[r], shift = shiftArr[r];
        int nb = 1 << bits;
        for (int i = tid; i < nb; i += nt) hist[i] = 0;
        if (tid == 0) s_sel = 0;
        __syncthreads();

        for (int i = tid; i < P; i += nt) {
            unsigned int v = sv[i];
            unsigned int hi = (r == 0) ? 0u : (v >> (shift + bits));
            if (hi == prefix) atomicAdd(&hist[(v >> shift) & (nb - 1)], 1);
        }
        __syncthreads();

        // inclusive suffix scan over hist[0..nb)
        for (int off = 1; off < nb; off <<= 1) {
            int i0 = tid, i1 = tid + nt;
            int v0 = 0, v1 = 0;
            if (i0 < nb) v0 = hist[i0] + ((i0 + off < nb) ? hist[i0 + off] : 0);
            if (i1 < nb) v1 = hist[i1] + ((i1 + off < nb) ? hist[i1 + off] : 0);
            __syncthreads();
            if (i0 < nb) hist[i0] = v0;
            if (i1 < nb) hist[i1] = v1;
            __syncthreads();
        }

        // d* = max d with suffix(d) >= kk
        if (tid < nb && hist[tid] >= kk) atomicMax(&s_sel, tid);
        {
            int i1 = tid + nt;
            if (i1 < nb && hist[i1] >= kk) atomicMax(&s_sel, i1);
        }
        __syncthreads();
        int d = s_sel;
        int above = (d + 1 < nb) ? hist[d + 1] : 0;
        kk -= above;
        prefix = (prefix << bits) | (unsigned int)d;
        __syncthreads();
    }

    unsigned int T = prefix;
    int c1 = 0; double s1 = 0.0;
    for (int i = tid; i < P; i += nt) {
        unsigned int v = sv[i];
        if (v > T) { c1++; s1 += (double)__uint_as_float(v); }
    }
    c1 = blockSumI(c1, s_ri);
    s1 = blockSumD(s1, s_rd);
    if (tid == 0)
        atomicAdd(&g_acc[2], s1 + (double)(k - c1) * (double)__uint_as_float(T));
}

// ---------------- kernel 5: finalize ----------------
__global__ void k_final(float* out, int B) {
    if (threadIdx.x == 0) {
        long long N = 0;
        for (int b = 0; b < B; b++) N += g_numpos[b];
        double Nd = (double)N;
        out[0] = (float)(g_acc[0] / Nd);
        out[1] = (float)((g_acc[1] + g_acc[2]) / Nd);
    }
}

// ---------------- launch ----------------
extern "C" void kernel_launch(void* const* d_in, const int* in_sizes, int n_in,
                              void* d_out, int out_size) {
    const float* conf   = (const float*)d_in[0];
    const float* loc    = (const float*)d_in[1];
    const float* priors = (const float*)d_in[2];
    const float* labels = (const float*)d_in[3];
    const int*   obj    = (const int*)d_in[4];

    int P = in_sizes[2] / 4;
    int B = in_sizes[4];
    int C = (int)((long long)in_sizes[0] / ((long long)B * P));
    int NMAX = in_sizes[3] / (B * 5);

    k_init<<<(B * NMAX + 255) / 256, 256>>>(B, NMAX);

    dim3 gm((P + 255) / 256, B);
    k_match<<<gm, 256>>>(priors, labels, obj, P, NMAX);

    k_override<<<B, NMAX>>>(obj, P, NMAX);

    dim3 gl((P + 127) / 128, B);
    if (C == 21) {
        k_loss<21><<<gl, 128>>>(conf, loc, priors, labels, P, NMAX);
    } else if (C == 81) {
        k_loss<81><<<gl, 128>>>(conf, loc, priors, labels, P, NMAX);
    }

    k_select<<<B, 1024>>>(P);
    k_final<<<1, 32>>>((float*)d_out, B);
}